// round 5
// baseline (speedup 1.0000x reference)
#include <cuda_runtime.h>
#include <cuda_bf16.h>
#include <cuda_fp16.h>
#include <math.h>
#include <stdint.h>

// ---------------------------------------------------------------------------
// HybridMambaBlock: B=2, L=1024, D_MODEL=768, D=1536, N=16, K_CONV=4, R=48
// p layout per token (52272): [z:0..1536) [u:1536..3072) [dth:3072..3120)
//                             [B:3120..27696) [C:27696..52272)
// ---------------------------------------------------------------------------

#define BATCH   2
#define SEQLEN  1024
#define NROWS   (BATCH*SEQLEN)      // 2048
#define DMODEL  768
#define DINNER  1536
#define NSTATE  16
#define DTRANK  48
#define PTOT    52272
#define OFF_Z   0
#define OFF_U   1536
#define OFF_DTH 3072
#define OFF_B   3120
#define OFF_C   27696

// scratch (device-global: no allocations allowed)
__device__ float g_p[(size_t)NROWS * PTOT];          // ~428 MB
__device__ float g_dtpre[(size_t)NROWS * DINNER];
__device__ float g_dt[(size_t)NROWS * DINNER];
__device__ float g_uc[(size_t)NROWS * DINNER];
__device__ float g_y[(size_t)NROWS * DINNER];
__device__ float g_res[(size_t)NROWS * DINNER];
__device__ __half g_wh[(size_t)PTOT * DMODEL];       // 80 MB fp16 W_in
__device__ __half g_xnh[(size_t)NROWS * DMODEL];
__device__ __half g_xnl[(size_t)NROWS * DMODEL];
__device__ __half g_xh[(size_t)NROWS * DMODEL];
__device__ __half g_xl[(size_t)NROWS * DMODEL];
__device__ __half g_wres[(size_t)DINNER * DMODEL];
__device__ __half g_wout[(size_t)DMODEL * DINNER];
__device__ __half g_gnh[(size_t)NROWS * DINNER];
__device__ __half g_gnl[(size_t)NROWS * DINNER];

// ---------------------------------------------------------------------------
// helpers
// ---------------------------------------------------------------------------
__device__ __forceinline__ uint32_t smem_u32(const void* p) {
    uint32_t a;
    asm("{ .reg .u64 t; cvta.to.shared.u64 t, %1; cvt.u32.u64 %0, t; }"
        : "=r"(a) : "l"(p));
    return a;
}

#define LDSM4(r0, r1, r2, r3, addr) \
    asm volatile("ldmatrix.sync.aligned.m8n8.x4.shared.b16 {%0,%1,%2,%3}, [%4];" \
        : "=r"(r0), "=r"(r1), "=r"(r2), "=r"(r3) : "r"(addr))

#define MMA16816F16(d, a, b) \
    asm volatile("mma.sync.aligned.m16n8k16.row.col.f32.f16.f16.f32 " \
        "{%0,%1,%2,%3}, {%4,%5,%6,%7}, {%8,%9}, {%0,%1,%2,%3};" \
        : "+f"((d)[0]), "+f"((d)[1]), "+f"((d)[2]), "+f"((d)[3]) \
        : "r"((a)[0]), "r"((a)[1]), "r"((a)[2]), "r"((a)[3]), \
          "r"((b)[0]), "r"((b)[1]))

#define CP_ASYNC16(dst, src, zf) \
    asm volatile("cp.async.cg.shared.global [%0], [%1], 16, %2;" \
        :: "r"(dst), "l"(src), "r"(zf))
#define CP_COMMIT()  asm volatile("cp.async.commit_group;" ::: "memory")
#define CP_WAIT1()   asm volatile("cp.async.wait_group 1;" ::: "memory")

// ---------------------------------------------------------------------------
// 2-term split-fp16 HMMA GEMM:  C[m,n] = sum_k (Ah+Al)[m,k] * Wh[n,k]
// CTA 128x128, BK=32, 2-stage cp.async double buffer, 8 warps of 32x64.
// 2 CTAs/SM (60KB smem each) -> 4 warps/SMSP to feed the HMMA pipe.
// lda = ldb = K, ldc = N. M % 128 == 0, K % 32 == 0. N-edge guarded.
// grid.x = M/128 (fast dim -> CTAs sharing W tile run in same wave)
// ---------------------------------------------------------------------------
#define ROWB    80
#define TILE_S  (128 * ROWB)         // 10240 B per 128x32 fp16 tile
#define STAGE_S (3 * TILE_S)         // Ah Al Wh
#define NSTG    2

__global__ void __launch_bounds__(256, 2) gemm2(
    const __half* __restrict__ Ah, const __half* __restrict__ Al,
    const __half* __restrict__ Wh, float* __restrict__ C,
    int N, int K, int kiter)
{
    extern __shared__ char sm[];
    uint32_t sb = smem_u32(sm);
    int tid = threadIdx.x;
    int wid = tid >> 5;
    int lane = tid & 31;
    int m0 = blockIdx.x * 128;
    int n0 = blockIdx.y * 128;

    int wm = wid >> 1;               // 0..3
    int wn = wid & 1;                // 0..1

    // ---- stage loader: 1536 x 16B cp.async, 6 per thread ----
    auto load_stage = [&](int stage, int k0) {
        uint32_t sdst = sb + stage * STAGE_S;
        #pragma unroll
        for (int j = 0; j < 6; j++) {
            int job = tid + j * 256;
            int tile = job >> 9;         // 0=Ah 1=Al 2=Wh
            int rem  = job & 511;
            int r    = rem >> 2;
            int cc   = rem & 3;
            const __half* src;
            int zf = 16;
            if (tile == 0)      src = Ah + (size_t)(m0 + r) * K + k0 + cc * 8;
            else if (tile == 1) src = Al + (size_t)(m0 + r) * K + k0 + cc * 8;
            else {
                int n = n0 + r;
                if (n >= N) { n = N - 1; zf = 0; }
                src = Wh + (size_t)n * K + k0 + cc * 8;
            }
            uint32_t d = sdst + tile * TILE_S + r * ROWB + cc * 16;
            CP_ASYNC16(d, src, zf);
        }
        CP_COMMIT();
    };

    float c[2][8][4];
    #pragma unroll
    for (int mt = 0; mt < 2; mt++)
        #pragma unroll
        for (int nt = 0; nt < 8; nt++)
            #pragma unroll
            for (int q = 0; q < 4; q++) c[mt][nt][q] = 0.f;

    load_stage(0, 0);

    for (int it = 0; it < kiter; it++) {
        // issue load of it+1 into the other buffer (free since it-1's compute
        // finished before the trailing __syncthreads of the previous iter)
        int k0n = (it + 1) * 32;
        if (k0n < K) load_stage((it + 1) & 1, k0n);
        else CP_COMMIT();               // keep group count consistent

        CP_WAIT1();                     // group it done; it+1 still in flight
        __syncthreads();

        uint32_t st = sb + (it & 1) * STAGE_S;

        #pragma unroll
        for (int kk = 0; kk < 32; kk += 16) {
            uint32_t aH[2][4], aL[2][4], bH[8][2];
            #pragma unroll
            for (int mt = 0; mt < 2; mt++) {
                int row = wm * 32 + mt * 16 + (lane & 15);
                int ch  = (kk >> 3) + (lane >> 4);
                uint32_t addr = st + row * ROWB + ch * 16;
                LDSM4(aH[mt][0], aH[mt][1], aH[mt][2], aH[mt][3], addr);
                LDSM4(aL[mt][0], aL[mt][1], aL[mt][2], aL[mt][3], addr + TILE_S);
            }
            #pragma unroll
            for (int np = 0; np < 4; np++) {
                int nrow = wn * 64 + np * 16 + (lane & 7) + ((lane >> 4) << 3);
                int ch   = (kk >> 3) + ((lane >> 3) & 1);
                uint32_t addr = st + 2 * TILE_S + nrow * ROWB + ch * 16;
                LDSM4(bH[np * 2][0], bH[np * 2][1], bH[np * 2 + 1][0], bH[np * 2 + 1][1], addr);
            }
            #pragma unroll
            for (int mt = 0; mt < 2; mt++)
                #pragma unroll
                for (int nt = 0; nt < 8; nt++) {
                    MMA16816F16(c[mt][nt], aH[mt], bH[nt]);
                    MMA16816F16(c[mt][nt], aL[mt], bH[nt]);
                }
        }
        __syncthreads();
    }

    // epilogue
    int g = lane >> 2, t4 = lane & 3;
    #pragma unroll
    for (int mt = 0; mt < 2; mt++) {
        int row = m0 + wm * 32 + mt * 16 + g;
        #pragma unroll
        for (int nt = 0; nt < 8; nt++) {
            int col = n0 + wn * 64 + nt * 8 + t4 * 2;
            if (col < N) {
                float2 v0 = make_float2(c[mt][nt][0], c[mt][nt][1]);
                float2 v1 = make_float2(c[mt][nt][2], c[mt][nt][3]);
                *(float2*)(C + (size_t)row * N + col) = v0;
                *(float2*)(C + (size_t)(row + 8) * N + col) = v1;
            }
        }
    }
}

// ---------------------------------------------------------------------------
// fp32 -> fp16 (hi only)
// ---------------------------------------------------------------------------
__global__ void __launch_bounds__(256) convert_h(
    const float* __restrict__ W, __half* __restrict__ Wh)
{
    size_t i4 = (size_t)blockIdx.x * 256 + threadIdx.x;
    float4 v = ((const float4*)W)[i4];
    __half2* o = (__half2*)Wh;
    o[i4 * 2 + 0] = __floats2half2_rn(v.x, v.y);
    o[i4 * 2 + 1] = __floats2half2_rn(v.z, v.w);
}

// ---------------------------------------------------------------------------
// fp32 -> (hi, lo) fp16 split
// ---------------------------------------------------------------------------
__global__ void __launch_bounds__(256) convert_split(
    const float* __restrict__ X, __half* __restrict__ Xh, __half* __restrict__ Xl)
{
    size_t i4 = (size_t)blockIdx.x * 256 + threadIdx.x;
    float4 v = ((const float4*)X)[i4];
    __half h0 = __float2half_rn(v.x), h1 = __float2half_rn(v.y);
    __half h2 = __float2half_rn(v.z), h3 = __float2half_rn(v.w);
    __half2* oh = (__half2*)Xh;
    __half2* ol = (__half2*)Xl;
    oh[i4 * 2 + 0] = __halves2half2(h0, h1);
    oh[i4 * 2 + 1] = __halves2half2(h2, h3);
    ol[i4 * 2 + 0] = __floats2half2_rn(v.x - __half2float(h0), v.y - __half2float(h1));
    ol[i4 * 2 + 1] = __floats2half2_rn(v.z - __half2float(h2), v.w - __half2float(h3));
}

// ---------------------------------------------------------------------------
// block reduction helper (256 threads)
// ---------------------------------------------------------------------------
__device__ __forceinline__ float block_reduce_sum256(float v, float* sh) {
    int lane = threadIdx.x & 31;
    int w    = threadIdx.x >> 5;
    #pragma unroll
    for (int o = 16; o > 0; o >>= 1) v += __shfl_xor_sync(0xffffffffu, v, o);
    if (lane == 0) sh[w] = v;
    __syncthreads();
    if (w == 0) {
        v = (lane < 8) ? sh[lane] : 0.0f;
        #pragma unroll
        for (int o = 4; o > 0; o >>= 1) v += __shfl_xor_sync(0xffffffffu, v, o);
        if (lane == 0) sh[0] = v;
    }
    __syncthreads();
    return sh[0];
}

// ---------------------------------------------------------------------------
// LayerNorm: one block per row of 768; outputs split-fp16
// ---------------------------------------------------------------------------
__global__ void __launch_bounds__(256) ln_kernel(
    const float* __restrict__ x, const float* __restrict__ w,
    const float* __restrict__ b, __half* __restrict__ oh,
    __half* __restrict__ ol)
{
    __shared__ float sh[32];
    int r = blockIdx.x;
    const float* xr = x + (size_t)r * DMODEL;
    float s = 0.f, ss = 0.f;
    float v[3];
    #pragma unroll
    for (int i = 0; i < 3; i++) {
        v[i] = xr[threadIdx.x + i * 256];
        s  += v[i];
        ss += v[i] * v[i];
    }
    s  = block_reduce_sum256(s, sh);
    __syncthreads();
    ss = block_reduce_sum256(ss, sh);
    float mu  = s * (1.0f / DMODEL);
    float var = ss * (1.0f / DMODEL) - mu * mu;
    float inv = rsqrtf(var + 1e-5f);
    #pragma unroll
    for (int i = 0; i < 3; i++) {
        int c = threadIdx.x + i * 256;
        float val = (v[i] - mu) * inv * w[c] + b[c];
        __half h = __float2half_rn(val);
        oh[(size_t)r * DMODEL + c] = h;
        ol[(size_t)r * DMODEL + c] = __float2half_rn(val - __half2float(h));
    }
}

// ---------------------------------------------------------------------------
// SIMT fp32 GEMM (dt projection only, K=48): C[m,n] = sum_k A[m,k]*B[n,k]
// ---------------------------------------------------------------------------
#define GBM 128
#define GBN 128
#define GBK 16
__global__ void __launch_bounds__(256) gemm_nt(
    const float* __restrict__ A, const float* __restrict__ B,
    float* __restrict__ C, int M, int N, int K, int lda, int ldb, int ldc)
{
    __shared__ float As[GBK][GBM + 4];
    __shared__ float Bs[GBK][GBN + 4];

    int tid = threadIdx.x;
    int tx = tid & 15;
    int ty = tid >> 4;
    int m0 = blockIdx.y * GBM;
    int n0 = blockIdx.x * GBN;
    int lrow = tid >> 2;
    int lc4  = tid & 3;

    float acc[8][8];
    #pragma unroll
    for (int i = 0; i < 8; i++)
        #pragma unroll
        for (int j = 0; j < 8; j++) acc[i][j] = 0.f;

    for (int k0 = 0; k0 < K; k0 += GBK) {
        #pragma unroll
        for (int i = 0; i < 2; i++) {
            int row = lrow + i * 64;
            float4 v = *(const float4*)(A + (size_t)(m0 + row) * lda + k0 + lc4 * 4);
            As[lc4 * 4 + 0][row] = v.x;
            As[lc4 * 4 + 1][row] = v.y;
            As[lc4 * 4 + 2][row] = v.z;
            As[lc4 * 4 + 3][row] = v.w;
        }
        #pragma unroll
        for (int i = 0; i < 2; i++) {
            int row = lrow + i * 64;
            int n = n0 + row;
            float4 v = make_float4(0.f, 0.f, 0.f, 0.f);
            if (n < N)
                v = *(const float4*)(B + (size_t)n * ldb + k0 + lc4 * 4);
            Bs[lc4 * 4 + 0][row] = v.x;
            Bs[lc4 * 4 + 1][row] = v.y;
            Bs[lc4 * 4 + 2][row] = v.z;
            Bs[lc4 * 4 + 3][row] = v.w;
        }
        __syncthreads();
        #pragma unroll
        for (int kk = 0; kk < GBK; kk++) {
            float a[8], b[8];
            #pragma unroll
            for (int i = 0; i < 8; i++) a[i] = As[kk][ty * 8 + i];
            #pragma unroll
            for (int j = 0; j < 8; j++) b[j] = Bs[kk][tx * 8 + j];
            #pragma unroll
            for (int i = 0; i < 8; i++)
                #pragma unroll
                for (int j = 0; j < 8; j++)
                    acc[i][j] = fmaf(a[i], b[j], acc[i][j]);
        }
        __syncthreads();
    }

    #pragma unroll
    for (int i = 0; i < 8; i++) {
        int m = m0 + ty * 8 + i;
        float* cp = C + (size_t)m * ldc + n0 + tx * 8;
        float4 v0 = make_float4(acc[i][0], acc[i][1], acc[i][2], acc[i][3]);
        float4 v1 = make_float4(acc[i][4], acc[i][5], acc[i][6], acc[i][7]);
        *(float4*)(cp + 0) = v0;
        *(float4*)(cp + 4) = v1;
    }
}

// ---------------------------------------------------------------------------
// Depthwise causal conv (K=4) + dt = clip(softplus(dtpre + dt_bias))
// ---------------------------------------------------------------------------
__global__ void __launch_bounds__(256) convdt_kernel(
    const float* __restrict__ conv_w, const float* __restrict__ conv_b,
    const float* __restrict__ dt_bias,
    const float* __restrict__ p, const float* __restrict__ dtpre,
    float* __restrict__ uc, float* __restrict__ dt)
{
    int idx = blockIdx.x * 256 + threadIdx.x;
    int d = idx % DINNER;
    int r = idx / DINNER;
    int l = r & (SEQLEN - 1);

    const float* pu = p + (size_t)r * PTOT + OFF_U + d;
    float acc = conv_b[d];
    #pragma unroll
    for (int k = 0; k < 4; k++) {
        int lp = l - 3 + k;
        if (lp >= 0)
            acc = fmaf(pu[(ptrdiff_t)(k - 3) * PTOT], conv_w[d * 4 + k], acc);
    }
    uc[idx] = acc;

    float xv = dtpre[idx] + dt_bias[d];
    float sp = fmaxf(xv, 0.f) + log1pf(expf(-fabsf(xv)));
    dt[idx] = fminf(fmaxf(sp, 1e-4f), 1.0f);
}

// ---------------------------------------------------------------------------
// SSM scan: 16 threads per (b,d)
// ---------------------------------------------------------------------------
__global__ void __launch_bounds__(256) scan_kernel(
    const float* __restrict__ p, const float* __restrict__ dt,
    const float* __restrict__ uc, const float* __restrict__ A_log,
    const float* __restrict__ Dskip, float* __restrict__ y)
{
    int tid = threadIdx.x;
    int n = tid & 15;
    int g = tid >> 4;
    int d = blockIdx.x * 16 + g;
    int b = blockIdx.y;

    float Ad  = -expf(A_log[d * NSTATE + n]);
    float dsk = Dskip[d];
    float h = 0.f;

    const float* pB  = p  + (size_t)(b * SEQLEN) * PTOT + OFF_B + d * NSTATE + n;
    const float* pC  = pB + (OFF_C - OFF_B);
    const float* pdt = dt + (size_t)(b * SEQLEN) * DINNER + d;
    const float* puc = uc + (size_t)(b * SEQLEN) * DINNER + d;
    float*       py  = y  + (size_t)(b * SEQLEN) * DINNER + d;

    for (int t = 0; t < SEQLEN; t++) {
        float dtv = __ldg(pdt);
        float ucv = __ldg(puc);
        float Bv  = __ldg(pB);
        float Cv  = __ldg(pC);
        float dA  = expf(dtv * Ad);
        h = fmaf(dA, h, dtv * ucv * Bv);
        float part = Cv * h;
        part += __shfl_xor_sync(0xffffffffu, part, 8, 16);
        part += __shfl_xor_sync(0xffffffffu, part, 4, 16);
        part += __shfl_xor_sync(0xffffffffu, part, 2, 16);
        part += __shfl_xor_sync(0xffffffffu, part, 1, 16);
        if (n == 0) *py = fmaf(dsk, ucv, part);
        pB += PTOT; pC += PTOT; pdt += DINNER; puc += DINNER; py += DINNER;
    }
}

// ---------------------------------------------------------------------------
// gate: g = y*silu(z); gn = g * rsqrt(mean(g^2)+1e-6) * norm_w + res
// outputs split-fp16 for the output projection
// ---------------------------------------------------------------------------
__global__ void __launch_bounds__(256) gate_kernel(
    const float* __restrict__ p, const float* __restrict__ y,
    const float* __restrict__ res, const float* __restrict__ norm_w,
    __half* __restrict__ gnh, __half* __restrict__ gnl)
{
    __shared__ float sh[32];
    int r = blockIdx.x;
    const float* zrow = p + (size_t)r * PTOT + OFF_Z;
    const float* yrow = y + (size_t)r * DINNER;
    float gv[6];
    float ss = 0.f;
    #pragma unroll
    for (int i = 0; i < 6; i++) {
        int c = threadIdx.x + i * 256;
        float z = zrow[c];
        float sil = z / (1.f + expf(-z));
        float gg = yrow[c] * sil;
        gv[i] = gg;
        ss += gg * gg;
    }
    ss = block_reduce_sum256(ss, sh);
    float s = rsqrtf(ss * (1.0f / DINNER) + 1e-6f);
    #pragma unroll
    for (int i = 0; i < 6; i++) {
        int c = threadIdx.x + i * 256;
        float val = gv[i] * s * norm_w[c] + res[(size_t)r * DINNER + c];
        __half h = __float2half_rn(val);
        gnh[(size_t)r * DINNER + c] = h;
        gnl[(size_t)r * DINNER + c] = __float2half_rn(val - __half2float(h));
    }
}

// ---------------------------------------------------------------------------
// host
// ---------------------------------------------------------------------------
extern "C" void kernel_launch(void* const* d_in, const int* in_sizes, int n_in,
                              void* d_out, int out_size)
{
    const float* x       = (const float*)d_in[0];
    const float* ln_w    = (const float*)d_in[1];
    const float* ln_b    = (const float*)d_in[2];
    const float* W_in    = (const float*)d_in[3];
    const float* W_dt    = (const float*)d_in[4];
    const float* conv_w  = (const float*)d_in[5];
    const float* conv_b  = (const float*)d_in[6];
    const float* A_log   = (const float*)d_in[7];
    const float* Dskip   = (const float*)d_in[8];
    const float* dt_bias = (const float*)d_in[9];
    const float* norm_w  = (const float*)d_in[10];
    const float* W_res   = (const float*)d_in[11];
    const float* W_out   = (const float*)d_in[12];
    float* out = (float*)d_out;

    float *p, *dtpre, *dt, *uc, *y, *res;
    __half *wh, *xnh, *xnl, *xh, *xl, *wres, *wout, *gnh, *gnl;
    cudaGetSymbolAddress((void**)&p,     g_p);
    cudaGetSymbolAddress((void**)&dtpre, g_dtpre);
    cudaGetSymbolAddress((void**)&dt,    g_dt);
    cudaGetSymbolAddress((void**)&uc,    g_uc);
    cudaGetSymbolAddress((void**)&y,     g_y);
    cudaGetSymbolAddress((void**)&res,   g_res);
    cudaGetSymbolAddress((void**)&wh,    g_wh);
    cudaGetSymbolAddress((void**)&xnh,   g_xnh);
    cudaGetSymbolAddress((void**)&xnl,   g_xnl);
    cudaGetSymbolAddress((void**)&xh,    g_xh);
    cudaGetSymbolAddress((void**)&xl,    g_xl);
    cudaGetSymbolAddress((void**)&wres,  g_wres);
    cudaGetSymbolAddress((void**)&wout,  g_wout);
    cudaGetSymbolAddress((void**)&gnh,   g_gnh);
    cudaGetSymbolAddress((void**)&gnl,   g_gnl);

    static bool attr_set = false;
    if (!attr_set) {
        cudaFuncSetAttribute(gemm2, cudaFuncAttributeMaxDynamicSharedMemorySize,
                             NSTG * STAGE_S);
        attr_set = true;
    }

    // 0. weight/input converts
    convert_h<<<(size_t)PTOT * DMODEL / 4 / 256, 256>>>(W_in, wh);
    convert_h<<<(size_t)DINNER * DMODEL / 4 / 256, 256>>>(W_res, wres);
    convert_h<<<(size_t)DMODEL * DINNER / 4 / 256, 256>>>(W_out, wout);
    convert_split<<<(size_t)NROWS * DMODEL / 4 / 256, 256>>>(x, xh, xl);

    // 1. LayerNorm (outputs split-fp16 xn)
    ln_kernel<<<NROWS, 256>>>(x, ln_w, ln_b, xnh, xnl);

    // 2. big input projection: p = xn @ W_in^T  [2048, 52272]
    gemm2<<<dim3(NROWS / 128, (PTOT + 127) / 128), 256, NSTG * STAGE_S>>>(
        xnh, xnl, wh, p, PTOT, DMODEL, DMODEL / 32);

    // 3. dt pre-projection: dtpre = dth @ W_dt^T  [2048, 1536], K=48
    gemm_nt<<<dim3(DINNER / GBN, NROWS / GBM), 256>>>(
        p + OFF_DTH, W_dt, dtpre, NROWS, DINNER, DTRANK, PTOT, DTRANK, DINNER);

    // 4. conv + softplus(dt)
    convdt_kernel<<<(NROWS * DINNER) / 256, 256>>>(
        conv_w, conv_b, dt_bias, p, dtpre, uc, dt);

    // 5. sequential SSM scan
    scan_kernel<<<dim3(DINNER / 16, BATCH), 256>>>(p, dt, uc, A_log, Dskip, y);

    // 6. residual projection: res = x @ W_res^T  [2048, 1536]
    gemm2<<<dim3(NROWS / 128, DINNER / 128), 256, NSTG * STAGE_S>>>(
        xh, xl, wres, res, DINNER, DMODEL, DMODEL / 32);

    // 7. gate + RMSNorm + residual (outputs split-fp16 gn)
    gate_kernel<<<NROWS, 256>>>(p, y, res, norm_w, gnh, gnl);

    // 8. output projection: out = gn @ W_out^T  [2048, 768]
    gemm2<<<dim3(NROWS / 128, DMODEL / 128), 256, NSTG * STAGE_S>>>(
        gnh, gnl, wout, out, DMODEL, DINNER, DINNER / 32);
}

// round 6
// speedup vs baseline: 1.5848x; 1.5848x over previous
#include <cuda_runtime.h>
#include <cuda_bf16.h>
#include <cuda_fp16.h>
#include <math.h>
#include <stdint.h>

// ---------------------------------------------------------------------------
// HybridMambaBlock: B=2, L=1024, D_MODEL=768, D=1536, N=16, K_CONV=4, R=48
// p layout per token (52272): [z:0..1536) [u:1536..3072) [dth:3072..3120)
//                             [B:3120..27696) [C:27696..52272)
// ---------------------------------------------------------------------------

#define BATCH   2
#define SEQLEN  1024
#define NROWS   (BATCH*SEQLEN)      // 2048
#define DMODEL  768
#define DINNER  1536
#define NSTATE  16
#define DTRANK  48
#define PTOT    52272
#define OFF_Z   0
#define OFF_U   1536
#define OFF_DTH 3072
#define OFF_B   3120
#define OFF_C   27696

// scratch (device-global: no allocations allowed)
__device__ float g_p[(size_t)NROWS * PTOT];          // ~428 MB
__device__ float g_dtpre[(size_t)NROWS * DINNER];
__device__ float g_dt[(size_t)NROWS * DINNER];
__device__ float g_uc[(size_t)NROWS * DINNER];
__device__ float g_y[(size_t)NROWS * DINNER];
__device__ float g_res[(size_t)NROWS * DINNER];
__device__ __half g_wh[(size_t)PTOT * DMODEL];       // 80 MB fp16 W_in
__device__ __half g_xnh[(size_t)NROWS * DMODEL];
__device__ __half g_xh[(size_t)NROWS * DMODEL];
__device__ __half g_xl[(size_t)NROWS * DMODEL];
__device__ __half g_wres[(size_t)DINNER * DMODEL];
__device__ __half g_wout[(size_t)DMODEL * DINNER];
__device__ __half g_gnh[(size_t)NROWS * DINNER];
__device__ __half g_gnl[(size_t)NROWS * DINNER];

// ---------------------------------------------------------------------------
// helpers
// ---------------------------------------------------------------------------
__device__ __forceinline__ uint32_t smem_u32(const void* p) {
    uint32_t a;
    asm("{ .reg .u64 t; cvta.to.shared.u64 t, %1; cvt.u32.u64 %0, t; }"
        : "=r"(a) : "l"(p));
    return a;
}

#define LDSM4(r0, r1, r2, r3, addr) \
    asm volatile("ldmatrix.sync.aligned.m8n8.x4.shared.b16 {%0,%1,%2,%3}, [%4];" \
        : "=r"(r0), "=r"(r1), "=r"(r2), "=r"(r3) : "r"(addr))

#define MMA16816F16(d, a, b) \
    asm volatile("mma.sync.aligned.m16n8k16.row.col.f32.f16.f16.f32 " \
        "{%0,%1,%2,%3}, {%4,%5,%6,%7}, {%8,%9}, {%0,%1,%2,%3};" \
        : "+f"((d)[0]), "+f"((d)[1]), "+f"((d)[2]), "+f"((d)[3]) \
        : "r"((a)[0]), "r"((a)[1]), "r"((a)[2]), "r"((a)[3]), \
          "r"((b)[0]), "r"((b)[1]))

#define CP_ASYNC16(dst, src, zf) \
    asm volatile("cp.async.cg.shared.global [%0], [%1], 16, %2;" \
        :: "r"(dst), "l"(src), "r"(zf))
#define CP_COMMIT()  asm volatile("cp.async.commit_group;" ::: "memory")
#define CP_WAIT1()   asm volatile("cp.async.wait_group 1;" ::: "memory")

#define ROWB    80
#define TILE_S  (128 * ROWB)         // 10240 B per 128x32 fp16 tile
#define NSTG    3

// ---------------------------------------------------------------------------
// 1-term fp16 HMMA GEMM (big projection):  C[m,n] = sum_k Ah[m,k] * Wh[n,k]
// CTA 128x128, BK=32, 3-stage cp.async, 8 warps of 32x64. Round-4 structure.
// ---------------------------------------------------------------------------
#define STAGE1_S (2 * TILE_S)        // Ah Wh

__global__ void __launch_bounds__(256, 1) gemm1(
    const __half* __restrict__ Ah, const __half* __restrict__ Wh,
    float* __restrict__ C, int N, int K, int kiter)
{
    extern __shared__ char sm[];
    uint32_t sb = smem_u32(sm);
    int tid = threadIdx.x;
    int wid = tid >> 5;
    int lane = tid & 31;
    int m0 = blockIdx.x * 128;
    int n0 = blockIdx.y * 128;
    int wm = wid >> 1;
    int wn = wid & 1;

    auto load_stage = [&](int stage, int k0) {
        uint32_t sdst = sb + stage * STAGE1_S;
        #pragma unroll
        for (int j = 0; j < 4; j++) {
            int job = tid + j * 256;     // 0..1023
            int tile = job >> 9;         // 0=Ah 1=Wh
            int rem  = job & 511;
            int r    = rem >> 2;
            int cc   = rem & 3;
            const __half* src;
            int zf = 16;
            if (tile == 0) src = Ah + (size_t)(m0 + r) * K + k0 + cc * 8;
            else {
                int n = n0 + r;
                if (n >= N) { n = N - 1; zf = 0; }
                src = Wh + (size_t)n * K + k0 + cc * 8;
            }
            uint32_t d = sdst + tile * TILE_S + r * ROWB + cc * 16;
            CP_ASYNC16(d, src, zf);
        }
        CP_COMMIT();
    };

    float c[2][8][4];
    #pragma unroll
    for (int mt = 0; mt < 2; mt++)
        #pragma unroll
        for (int nt = 0; nt < 8; nt++)
            #pragma unroll
            for (int q = 0; q < 4; q++) c[mt][nt][q] = 0.f;

    load_stage(0, 0);
    load_stage(1, 32);

    for (int it = 0; it < kiter; it++) {
        CP_WAIT1();
        __syncthreads();

        int k0n = (it + 2) * 32;
        if (k0n < K) load_stage((it + 2) % NSTG, k0n);
        else CP_COMMIT();

        uint32_t st = sb + (it % NSTG) * STAGE1_S;

        #pragma unroll
        for (int kk = 0; kk < 32; kk += 16) {
            uint32_t aH[2][4], bH[8][2];
            #pragma unroll
            for (int mt = 0; mt < 2; mt++) {
                int row = wm * 32 + mt * 16 + (lane & 15);
                int ch  = (kk >> 3) + (lane >> 4);
                uint32_t addr = st + row * ROWB + ch * 16;
                LDSM4(aH[mt][0], aH[mt][1], aH[mt][2], aH[mt][3], addr);
            }
            #pragma unroll
            for (int np = 0; np < 4; np++) {
                int nrow = wn * 64 + np * 16 + (lane & 7) + ((lane >> 4) << 3);
                int ch   = (kk >> 3) + ((lane >> 3) & 1);
                uint32_t addr = st + TILE_S + nrow * ROWB + ch * 16;
                LDSM4(bH[np * 2][0], bH[np * 2][1], bH[np * 2 + 1][0], bH[np * 2 + 1][1], addr);
            }
            #pragma unroll
            for (int mt = 0; mt < 2; mt++)
                #pragma unroll
                for (int nt = 0; nt < 8; nt++)
                    MMA16816F16(c[mt][nt], aH[mt], bH[nt]);
        }
        __syncthreads();
    }

    int g = lane >> 2, t4 = lane & 3;
    #pragma unroll
    for (int mt = 0; mt < 2; mt++) {
        int row = m0 + wm * 32 + mt * 16 + g;
        #pragma unroll
        for (int nt = 0; nt < 8; nt++) {
            int col = n0 + wn * 64 + nt * 8 + t4 * 2;
            if (col < N) {
                float2 v0 = make_float2(c[mt][nt][0], c[mt][nt][1]);
                float2 v1 = make_float2(c[mt][nt][2], c[mt][nt][3]);
                *(float2*)(C + (size_t)row * N + col) = v0;
                *(float2*)(C + (size_t)(row + 8) * N + col) = v1;
            }
        }
    }
}

// ---------------------------------------------------------------------------
// 2-term split-fp16 HMMA GEMM (res/out): C = (Ah+Al) @ Wh^T  (Round-4 exact)
// ---------------------------------------------------------------------------
#define STAGE2_S (3 * TILE_S)        // Ah Al Wh

__global__ void __launch_bounds__(256, 1) gemm2(
    const __half* __restrict__ Ah, const __half* __restrict__ Al,
    const __half* __restrict__ Wh, float* __restrict__ C,
    int N, int K, int kiter)
{
    extern __shared__ char sm[];
    uint32_t sb = smem_u32(sm);
    int tid = threadIdx.x;
    int wid = tid >> 5;
    int lane = tid & 31;
    int m0 = blockIdx.x * 128;
    int n0 = blockIdx.y * 128;
    int wm = wid >> 1;
    int wn = wid & 1;

    auto load_stage = [&](int stage, int k0) {
        uint32_t sdst = sb + stage * STAGE2_S;
        #pragma unroll
        for (int j = 0; j < 6; j++) {
            int job = tid + j * 256;
            int tile = job >> 9;         // 0=Ah 1=Al 2=Wh
            int rem  = job & 511;
            int r    = rem >> 2;
            int cc   = rem & 3;
            const __half* src;
            int zf = 16;
            if (tile == 0)      src = Ah + (size_t)(m0 + r) * K + k0 + cc * 8;
            else if (tile == 1) src = Al + (size_t)(m0 + r) * K + k0 + cc * 8;
            else {
                int n = n0 + r;
                if (n >= N) { n = N - 1; zf = 0; }
                src = Wh + (size_t)n * K + k0 + cc * 8;
            }
            uint32_t d = sdst + tile * TILE_S + r * ROWB + cc * 16;
            CP_ASYNC16(d, src, zf);
        }
        CP_COMMIT();
    };

    float c[2][8][4];
    #pragma unroll
    for (int mt = 0; mt < 2; mt++)
        #pragma unroll
        for (int nt = 0; nt < 8; nt++)
            #pragma unroll
            for (int q = 0; q < 4; q++) c[mt][nt][q] = 0.f;

    load_stage(0, 0);
    load_stage(1, 32);

    for (int it = 0; it < kiter; it++) {
        CP_WAIT1();
        __syncthreads();

        int k0n = (it + 2) * 32;
        if (k0n < K) load_stage((it + 2) % NSTG, k0n);
        else CP_COMMIT();

        uint32_t st = sb + (it % NSTG) * STAGE2_S;

        #pragma unroll
        for (int kk = 0; kk < 32; kk += 16) {
            uint32_t aH[2][4], aL[2][4], bH[8][2];
            #pragma unroll
            for (int mt = 0; mt < 2; mt++) {
                int row = wm * 32 + mt * 16 + (lane & 15);
                int ch  = (kk >> 3) + (lane >> 4);
                uint32_t addr = st + row * ROWB + ch * 16;
                LDSM4(aH[mt][0], aH[mt][1], aH[mt][2], aH[mt][3], addr);
                LDSM4(aL[mt][0], aL[mt][1], aL[mt][2], aL[mt][3], addr + TILE_S);
            }
            #pragma unroll
            for (int np = 0; np < 4; np++) {
                int nrow = wn * 64 + np * 16 + (lane & 7) + ((lane >> 4) << 3);
                int ch   = (kk >> 3) + ((lane >> 3) & 1);
                uint32_t addr = st + 2 * TILE_S + nrow * ROWB + ch * 16;
                LDSM4(bH[np * 2][0], bH[np * 2][1], bH[np * 2 + 1][0], bH[np * 2 + 1][1], addr);
            }
            #pragma unroll
            for (int mt = 0; mt < 2; mt++)
                #pragma unroll
                for (int nt = 0; nt < 8; nt++) {
                    MMA16816F16(c[mt][nt], aH[mt], bH[nt]);
                    MMA16816F16(c[mt][nt], aL[mt], bH[nt]);
                }
        }
        __syncthreads();
    }

    int g = lane >> 2, t4 = lane & 3;
    #pragma unroll
    for (int mt = 0; mt < 2; mt++) {
        int row = m0 + wm * 32 + mt * 16 + g;
        #pragma unroll
        for (int nt = 0; nt < 8; nt++) {
            int col = n0 + wn * 64 + nt * 8 + t4 * 2;
            if (col < N) {
                float2 v0 = make_float2(c[mt][nt][0], c[mt][nt][1]);
                float2 v1 = make_float2(c[mt][nt][2], c[mt][nt][3]);
                *(float2*)(C + (size_t)row * N + col) = v0;
                *(float2*)(C + (size_t)(row + 8) * N + col) = v1;
            }
        }
    }
}

// ---------------------------------------------------------------------------
// fp32 -> fp16 (hi only)
// ---------------------------------------------------------------------------
__global__ void __launch_bounds__(256) convert_h(
    const float* __restrict__ W, __half* __restrict__ Wh)
{
    size_t i4 = (size_t)blockIdx.x * 256 + threadIdx.x;
    float4 v = ((const float4*)W)[i4];
    __half2* o = (__half2*)Wh;
    o[i4 * 2 + 0] = __floats2half2_rn(v.x, v.y);
    o[i4 * 2 + 1] = __floats2half2_rn(v.z, v.w);
}

// ---------------------------------------------------------------------------
// fp32 -> (hi, lo) fp16 split
// ---------------------------------------------------------------------------
__global__ void __launch_bounds__(256) convert_split(
    const float* __restrict__ X, __half* __restrict__ Xh, __half* __restrict__ Xl)
{
    size_t i4 = (size_t)blockIdx.x * 256 + threadIdx.x;
    float4 v = ((const float4*)X)[i4];
    __half h0 = __float2half_rn(v.x), h1 = __float2half_rn(v.y);
    __half h2 = __float2half_rn(v.z), h3 = __float2half_rn(v.w);
    __half2* oh = (__half2*)Xh;
    __half2* ol = (__half2*)Xl;
    oh[i4 * 2 + 0] = __halves2half2(h0, h1);
    oh[i4 * 2 + 1] = __halves2half2(h2, h3);
    ol[i4 * 2 + 0] = __floats2half2_rn(v.x - __half2float(h0), v.y - __half2float(h1));
    ol[i4 * 2 + 1] = __floats2half2_rn(v.z - __half2float(h2), v.w - __half2float(h3));
}

// ---------------------------------------------------------------------------
// block reduction helper (256 threads)
// ---------------------------------------------------------------------------
__device__ __forceinline__ float block_reduce_sum256(float v, float* sh) {
    int lane = threadIdx.x & 31;
    int w    = threadIdx.x >> 5;
    #pragma unroll
    for (int o = 16; o > 0; o >>= 1) v += __shfl_xor_sync(0xffffffffu, v, o);
    if (lane == 0) sh[w] = v;
    __syncthreads();
    if (w == 0) {
        v = (lane < 8) ? sh[lane] : 0.0f;
        #pragma unroll
        for (int o = 4; o > 0; o >>= 1) v += __shfl_xor_sync(0xffffffffu, v, o);
        if (lane == 0) sh[0] = v;
    }
    __syncthreads();
    return sh[0];
}

// ---------------------------------------------------------------------------
// LayerNorm: one block per row of 768; outputs fp16 xn
// ---------------------------------------------------------------------------
__global__ void __launch_bounds__(256) ln_kernel(
    const float* __restrict__ x, const float* __restrict__ w,
    const float* __restrict__ b, __half* __restrict__ oh)
{
    __shared__ float sh[32];
    int r = blockIdx.x;
    const float* xr = x + (size_t)r * DMODEL;
    float s = 0.f, ss = 0.f;
    float v[3];
    #pragma unroll
    for (int i = 0; i < 3; i++) {
        v[i] = xr[threadIdx.x + i * 256];
        s  += v[i];
        ss += v[i] * v[i];
    }
    s  = block_reduce_sum256(s, sh);
    __syncthreads();
    ss = block_reduce_sum256(ss, sh);
    float mu  = s * (1.0f / DMODEL);
    float var = ss * (1.0f / DMODEL) - mu * mu;
    float inv = rsqrtf(var + 1e-5f);
    #pragma unroll
    for (int i = 0; i < 3; i++) {
        int c = threadIdx.x + i * 256;
        float val = (v[i] - mu) * inv * w[c] + b[c];
        oh[(size_t)r * DMODEL + c] = __float2half_rn(val);
    }
}

// ---------------------------------------------------------------------------
// SIMT fp32 GEMM (dt projection only, K=48): C[m,n] = sum_k A[m,k]*B[n,k]
// ---------------------------------------------------------------------------
#define GBM 128
#define GBN 128
#define GBK 16
__global__ void __launch_bounds__(256) gemm_nt(
    const float* __restrict__ A, const float* __restrict__ B,
    float* __restrict__ C, int M, int N, int K, int lda, int ldb, int ldc)
{
    __shared__ float As[GBK][GBM + 4];
    __shared__ float Bs[GBK][GBN + 4];

    int tid = threadIdx.x;
    int tx = tid & 15;
    int ty = tid >> 4;
    int m0 = blockIdx.y * GBM;
    int n0 = blockIdx.x * GBN;
    int lrow = tid >> 2;
    int lc4  = tid & 3;

    float acc[8][8];
    #pragma unroll
    for (int i = 0; i < 8; i++)
        #pragma unroll
        for (int j = 0; j < 8; j++) acc[i][j] = 0.f;

    for (int k0 = 0; k0 < K; k0 += GBK) {
        #pragma unroll
        for (int i = 0; i < 2; i++) {
            int row = lrow + i * 64;
            float4 v = *(const float4*)(A + (size_t)(m0 + row) * lda + k0 + lc4 * 4);
            As[lc4 * 4 + 0][row] = v.x;
            As[lc4 * 4 + 1][row] = v.y;
            As[lc4 * 4 + 2][row] = v.z;
            As[lc4 * 4 + 3][row] = v.w;
        }
        #pragma unroll
        for (int i = 0; i < 2; i++) {
            int row = lrow + i * 64;
            int n = n0 + row;
            float4 v = make_float4(0.f, 0.f, 0.f, 0.f);
            if (n < N)
                v = *(const float4*)(B + (size_t)n * ldb + k0 + lc4 * 4);
            Bs[lc4 * 4 + 0][row] = v.x;
            Bs[lc4 * 4 + 1][row] = v.y;
            Bs[lc4 * 4 + 2][row] = v.z;
            Bs[lc4 * 4 + 3][row] = v.w;
        }
        __syncthreads();
        #pragma unroll
        for (int kk = 0; kk < GBK; kk++) {
            float a[8], b[8];
            #pragma unroll
            for (int i = 0; i < 8; i++) a[i] = As[kk][ty * 8 + i];
            #pragma unroll
            for (int j = 0; j < 8; j++) b[j] = Bs[kk][tx * 8 + j];
            #pragma unroll
            for (int i = 0; i < 8; i++)
                #pragma unroll
                for (int j = 0; j < 8; j++)
                    acc[i][j] = fmaf(a[i], b[j], acc[i][j]);
        }
        __syncthreads();
    }

    #pragma unroll
    for (int i = 0; i < 8; i++) {
        int m = m0 + ty * 8 + i;
        float* cp = C + (size_t)m * ldc + n0 + tx * 8;
        float4 v0 = make_float4(acc[i][0], acc[i][1], acc[i][2], acc[i][3]);
        float4 v1 = make_float4(acc[i][4], acc[i][5], acc[i][6], acc[i][7]);
        *(float4*)(cp + 0) = v0;
        *(float4*)(cp + 4) = v1;
    }
}

// ---------------------------------------------------------------------------
// Depthwise causal conv (K=4) + dt = clip(softplus(dtpre + dt_bias))
// ---------------------------------------------------------------------------
__global__ void __launch_bounds__(256) convdt_kernel(
    const float* __restrict__ conv_w, const float* __restrict__ conv_b,
    const float* __restrict__ dt_bias,
    const float* __restrict__ p, const float* __restrict__ dtpre,
    float* __restrict__ uc, float* __restrict__ dt)
{
    int idx = blockIdx.x * 256 + threadIdx.x;
    int d = idx % DINNER;
    int r = idx / DINNER;
    int l = r & (SEQLEN - 1);

    const float* pu = p + (size_t)r * PTOT + OFF_U + d;
    float acc = conv_b[d];
    #pragma unroll
    for (int k = 0; k < 4; k++) {
        int lp = l - 3 + k;
        if (lp >= 0)
            acc = fmaf(pu[(ptrdiff_t)(k - 3) * PTOT], conv_w[d * 4 + k], acc);
    }
    uc[idx] = acc;

    float xv = dtpre[idx] + dt_bias[d];
    float sp = fmaxf(xv, 0.f) + log1pf(expf(-fabsf(xv)));
    dt[idx] = fminf(fmaxf(sp, 1e-4f), 1.0f);
}

// ---------------------------------------------------------------------------
// SSM scan: 16 threads per (b,d)
// ---------------------------------------------------------------------------
__global__ void __launch_bounds__(256) scan_kernel(
    const float* __restrict__ p, const float* __restrict__ dt,
    const float* __restrict__ uc, const float* __restrict__ A_log,
    const float* __restrict__ Dskip, float* __restrict__ y)
{
    int tid = threadIdx.x;
    int n = tid & 15;
    int g = tid >> 4;
    int d = blockIdx.x * 16 + g;
    int b = blockIdx.y;

    float Ad  = -expf(A_log[d * NSTATE + n]);
    float dsk = Dskip[d];
    float h = 0.f;

    const float* pB  = p  + (size_t)(b * SEQLEN) * PTOT + OFF_B + d * NSTATE + n;
    const float* pC  = pB + (OFF_C - OFF_B);
    const float* pdt = dt + (size_t)(b * SEQLEN) * DINNER + d;
    const float* puc = uc + (size_t)(b * SEQLEN) * DINNER + d;
    float*       py  = y  + (size_t)(b * SEQLEN) * DINNER + d;

    for (int t = 0; t < SEQLEN; t++) {
        float dtv = __ldg(pdt);
        float ucv = __ldg(puc);
        float Bv  = __ldg(pB);
        float Cv  = __ldg(pC);
        float dA  = expf(dtv * Ad);
        h = fmaf(dA, h, dtv * ucv * Bv);
        float part = Cv * h;
        part += __shfl_xor_sync(0xffffffffu, part, 8, 16);
        part += __shfl_xor_sync(0xffffffffu, part, 4, 16);
        part += __shfl_xor_sync(0xffffffffu, part, 2, 16);
        part += __shfl_xor_sync(0xffffffffu, part, 1, 16);
        if (n == 0) *py = fmaf(dsk, ucv, part);
        pB += PTOT; pC += PTOT; pdt += DINNER; puc += DINNER; py += DINNER;
    }
}

// ---------------------------------------------------------------------------
// gate: g = y*silu(z); gn = g * rsqrt(mean(g^2)+1e-6) * norm_w + res
// outputs split-fp16 for the output projection
// ---------------------------------------------------------------------------
__global__ void __launch_bounds__(256) gate_kernel(
    const float* __restrict__ p, const float* __restrict__ y,
    const float* __restrict__ res, const float* __restrict__ norm_w,
    __half* __restrict__ gnh, __half* __restrict__ gnl)
{
    __shared__ float sh[32];
    int r = blockIdx.x;
    const float* zrow = p + (size_t)r * PTOT + OFF_Z;
    const float* yrow = y + (size_t)r * DINNER;
    float gv[6];
    float ss = 0.f;
    #pragma unroll
    for (int i = 0; i < 6; i++) {
        int c = threadIdx.x + i * 256;
        float z = zrow[c];
        float sil = z / (1.f + expf(-z));
        float gg = yrow[c] * sil;
        gv[i] = gg;
        ss += gg * gg;
    }
    ss = block_reduce_sum256(ss, sh);
    float s = rsqrtf(ss * (1.0f / DINNER) + 1e-6f);
    #pragma unroll
    for (int i = 0; i < 6; i++) {
        int c = threadIdx.x + i * 256;
        float val = gv[i] * s * norm_w[c] + res[(size_t)r * DINNER + c];
        __half h = __float2half_rn(val);
        gnh[(size_t)r * DINNER + c] = h;
        gnl[(size_t)r * DINNER + c] = __float2half_rn(val - __half2float(h));
    }
}

// ---------------------------------------------------------------------------
// host
// ---------------------------------------------------------------------------
extern "C" void kernel_launch(void* const* d_in, const int* in_sizes, int n_in,
                              void* d_out, int out_size)
{
    const float* x       = (const float*)d_in[0];
    const float* ln_w    = (const float*)d_in[1];
    const float* ln_b    = (const float*)d_in[2];
    const float* W_in    = (const float*)d_in[3];
    const float* W_dt    = (const float*)d_in[4];
    const float* conv_w  = (const float*)d_in[5];
    const float* conv_b  = (const float*)d_in[6];
    const float* A_log   = (const float*)d_in[7];
    const float* Dskip   = (const float*)d_in[8];
    const float* dt_bias = (const float*)d_in[9];
    const float* norm_w  = (const float*)d_in[10];
    const float* W_res   = (const float*)d_in[11];
    const float* W_out   = (const float*)d_in[12];
    float* out = (float*)d_out;

    float *p, *dtpre, *dt, *uc, *y, *res;
    __half *wh, *xnh, *xh, *xl, *wres, *wout, *gnh, *gnl;
    cudaGetSymbolAddress((void**)&p,     g_p);
    cudaGetSymbolAddress((void**)&dtpre, g_dtpre);
    cudaGetSymbolAddress((void**)&dt,    g_dt);
    cudaGetSymbolAddress((void**)&uc,    g_uc);
    cudaGetSymbolAddress((void**)&y,     g_y);
    cudaGetSymbolAddress((void**)&res,   g_res);
    cudaGetSymbolAddress((void**)&wh,    g_wh);
    cudaGetSymbolAddress((void**)&xnh,   g_xnh);
    cudaGetSymbolAddress((void**)&xh,    g_xh);
    cudaGetSymbolAddress((void**)&xl,    g_xl);
    cudaGetSymbolAddress((void**)&wres,  g_wres);
    cudaGetSymbolAddress((void**)&wout,  g_wout);
    cudaGetSymbolAddress((void**)&gnh,   g_gnh);
    cudaGetSymbolAddress((void**)&gnl,   g_gnl);

    static bool attr_set = false;
    if (!attr_set) {
        cudaFuncSetAttribute(gemm1, cudaFuncAttributeMaxDynamicSharedMemorySize,
                             NSTG * STAGE1_S);
        cudaFuncSetAttribute(gemm2, cudaFuncAttributeMaxDynamicSharedMemorySize,
                             NSTG * STAGE2_S);
        attr_set = true;
    }

    // 0. weight/input converts
    convert_h<<<(size_t)PTOT * DMODEL / 4 / 256, 256>>>(W_in, wh);
    convert_h<<<(size_t)DINNER * DMODEL / 4 / 256, 256>>>(W_res, wres);
    convert_h<<<(size_t)DMODEL * DINNER / 4 / 256, 256>>>(W_out, wout);
    convert_split<<<(size_t)NROWS * DMODEL / 4 / 256, 256>>>(x, xh, xl);

    // 1. LayerNorm (outputs fp16 xn)
    ln_kernel<<<NROWS, 256>>>(x, ln_w, ln_b, xnh);

    // 2. big input projection (1-term fp16): p = xn @ W_in^T  [2048, 52272]
    gemm1<<<dim3(NROWS / 128, (PTOT + 127) / 128), 256, NSTG * STAGE1_S>>>(
        xnh, wh, p, PTOT, DMODEL, DMODEL / 32);

    // 3. dt pre-projection: dtpre = dth @ W_dt^T  [2048, 1536], K=48
    gemm_nt<<<dim3(DINNER / GBN, NROWS / GBM), 256>>>(
        p + OFF_DTH, W_dt, dtpre, NROWS, DINNER, DTRANK, PTOT, DTRANK, DINNER);

    // 4. conv + softplus(dt)
    convdt_kernel<<<(NROWS * DINNER) / 256, 256>>>(
        conv_w, conv_b, dt_bias, p, dtpre, uc, dt);

    // 5. sequential SSM scan
    scan_kernel<<<dim3(DINNER / 16, BATCH), 256>>>(p, dt, uc, A_log, Dskip, y);

    // 6. residual projection (2-term): res = x @ W_res^T  [2048, 1536]
    gemm2<<<dim3(NROWS / 128, DINNER / 128), 256, NSTG * STAGE2_S>>>(
        xh, xl, wres, res, DINNER, DMODEL, DMODEL / 32);

    // 7. gate + RMSNorm + residual (outputs split-fp16 gn)
    gate_kernel<<<NROWS, 256>>>(p, y, res, norm_w, gnh, gnl);

    // 8. output projection (2-term): out = gn @ W_out^T  [2048, 768]
    gemm2<<<dim3(NROWS / 128, DMODEL / 128), 256, NSTG * STAGE2_S>>>(
        gnh, gnl, wout, out, DMODEL, DINNER, DINNER / 32);
}